// round 15
// baseline (speedup 1.0000x reference)
#include <cuda_runtime.h>

typedef unsigned long long u64;

#define E_EDGES 320000
#define NTHR 128
#define NBLK (E_EDGES / NTHR)
#define SB_STRIDE 36   // floats; 144B rows, 16B-aligned

#define LOG2E   1.4426950408889634f
#define SELU_S  1.0507009873554805f
#define ALPHA_S 1.7580993408473766f                 // scale*alpha
#define C1      (1.0507009873554805f * 0.69314718055994530942f)  // s*ln2

// Scratch (device globals -- no allocation allowed)
__device__ __align__(16) float g_h [E_EDGES * 20];
__device__ __align__(16) float g_v0[E_EDGES * 32];
__device__ __align__(16) float g_v1[E_EDGES * 32];
__device__ __align__(16) float g_colsum[20];        // sum_c W2[c][o], computed once

// GRU weights in constant memory (populated via cudaMemcpyToSymbolAsync, D2D).
// ONLY the GRU lives here (R12: wider constant use serializes).
__constant__ ulonglong2 cWih[300];   // 60 rows x 20 floats
__constant__ ulonglong2 cWhh[300];

// ---- packed f32x2 helpers ----
__device__ __forceinline__ u64 fma2(u64 a, u64 b, u64 c) {
    u64 d; asm("fma.rn.f32x2 %0, %1, %2, %3;" : "=l"(d) : "l"(a), "l"(b), "l"(c)); return d;
}
__device__ __forceinline__ u64 add2(u64 a, u64 b) {
    u64 d; asm("add.rn.f32x2 %0, %1, %2;" : "=l"(d) : "l"(a), "l"(b)); return d;
}
__device__ __forceinline__ u64 pack2(float x, float y) {
    u64 d; asm("mov.b64 %0, {%1, %2};" : "=l"(d) : "f"(x), "f"(y)); return d;
}
__device__ __forceinline__ float2 unpack2(u64 v) {
    float2 r; asm("mov.b64 {%0, %1}, %2;" : "=f"(r.x), "=f"(r.y) : "l"(v)); return r;
}
__device__ __forceinline__ float ex2f(float x) {
    float y; asm("ex2.approx.f32 %0, %1;" : "=f"(y) : "f"(x)); return y;
}
__device__ __forceinline__ float tanhap(float x) {
    float y; asm("tanh.approx.f32 %0, %1;" : "=f"(y) : "f"(x)); return y;
}
__device__ __forceinline__ float sigmoid_t(float x) {
    return fmaf(tanhap(0.5f * x), 0.5f, 0.5f);   // exact identity, MUFU.TANH
}

// branchless SELU (no predicate dependency):
//   m = min(x,0);  selu = s*(x-m) + alpha_s*(2^(m*log2e) - 1)
__device__ __forceinline__ float selu_b(float x) {
    float m = fminf(x, 0.0f);
    return fmaf(SELU_S, x - m, fmaf(ALPHA_S, ex2f(m * LOG2E), -ALPHA_S));
}

// packed dot reading a 20-float row from __constant__
template<bool IH>
__device__ __forceinline__ float dot20c(int row, const u64* a) {
    u64 acc0 = 0ull, acc1 = 0ull;
#pragma unroll
    for (int q = 0; q < 5; q++) {
        ulonglong2 ww = IH ? cWih[row * 5 + q] : cWhh[row * 5 + q];
        acc0 = fma2(a[2*q],   ww.x, acc0);
        acc1 = fma2(a[2*q+1], ww.y, acc1);
    }
    float2 r0 = unpack2(acc0), r1 = unpack2(acc1);
    return (r0.x + r0.y) + (r1.x + r1.y);
}

// fused gate dot: wih_row . a  +  whh_row . b, one reduction
__device__ __forceinline__ float dot40c(int row, const u64* a, const u64* b) {
    u64 acc0 = 0ull, acc1 = 0ull;
#pragma unroll
    for (int q = 0; q < 5; q++) {
        ulonglong2 ww = cWih[row * 5 + q];
        acc0 = fma2(a[2*q],   ww.x, acc0);
        acc1 = fma2(a[2*q+1], ww.y, acc1);
    }
#pragma unroll
    for (int q = 0; q < 5; q++) {
        ulonglong2 ww = cWhh[row * 5 + q];
        acc0 = fma2(b[2*q],   ww.x, acc0);
        acc1 = fma2(b[2*q+1], ww.y, acc1);
    }
    float2 r0 = unpack2(acc0), r1 = unpack2(acc1);
    return (r0.x + r0.y) + (r1.x + r1.y);
}

// packed matvec: acc2[16] (32 outs) += hf * w_row[32]
__device__ __forceinline__ void mv32p(u64* acc2, float hf, const float* __restrict__ wrow) {
    u64 h2 = pack2(hf, hf);
    const ulonglong2* w = (const ulonglong2*)wrow;
#pragma unroll
    for (int q = 0; q < 8; q++) {
        ulonglong2 ww = w[q];
        acc2[2*q]   = fma2(h2, ww.x, acc2[2*q]);
        acc2[2*q+1] = fma2(h2, ww.y, acc2[2*q+1]);
    }
}

// ---------------------------------------------------------------------------
__global__ void __launch_bounds__(NTHR) kv_init(const float* __restrict__ ea,
                                                const float* __restrict__ W1,
                                                const float* __restrict__ W2) {
    __shared__ __align__(16) float sW1b[640];
    for (int i = threadIdx.x; i < 640; i += NTHR) sW1b[i] = W1[640 + i] * LOG2E;
    // one block computes W2 column sums once for all step kernels
    if (blockIdx.x == 0 && threadIdx.x < 20) {
        float ssum = 0.0f;
#pragma unroll
        for (int c = 0; c < 32; c++) ssum += __ldg(W2 + c * 20 + threadIdx.x);
        g_colsum[threadIdx.x] = ssum;
    }
    __syncthreads();

    int e = blockIdx.x * NTHR + threadIdx.x;
    u64 h2[10];
    {
        const ulonglong2* hp = (const ulonglong2*)(ea + (size_t)e * 20);
#pragma unroll
        for (int q = 0; q < 5; q++) { ulonglong2 t = hp[q]; h2[2*q] = t.x; h2[2*q+1] = t.y; }
    }
    u64 v2[16];
#pragma unroll
    for (int c = 0; c < 16; c++) v2[c] = 0ull;
#pragma unroll
    for (int fp = 0; fp < 10; fp++) {
        float2 hh = unpack2(h2[fp]);
        mv32p(v2, hh.x, sW1b + (2*fp)   * 32);
        mv32p(v2, hh.y, sW1b + (2*fp+1) * 32);
    }
    ulonglong2* vp = (ulonglong2*)(g_v0 + (size_t)e * 32);
#pragma unroll
    for (int q = 0; q < 8; q++) { ulonglong2 t; t.x = v2[2*q]; t.y = v2[2*q+1]; vp[q] = t; }
}

// ---------------------------------------------------------------------------
template<bool FIRST, bool COMPV>
__global__ void __launch_bounds__(NTHR, 7) step_kernel(
    const float* __restrict__ ea,
    const float* __restrict__ W1,  const float* __restrict__ b1,
    const float* __restrict__ W2,  const float* __restrict__ b2,
    const float* __restrict__ bih, const float* __restrict__ bhh,
    const int*   __restrict__ dstv,
    int parity)
{
    __shared__ __align__(16) float sW1a[640];   // pre-scaled by log2e
    __shared__ __align__(16) float sW1b[640];   // pre-scaled by log2e
    __shared__ __align__(16) float sW2 [640];
    __shared__ __align__(16) float sb1[32];     // pre-scaled by log2e
    __shared__ __align__(16) float sb2a[20];    // 16*b2 - 16*ALPHA_S*colsum
    __shared__ float sbc[40];                    // bih+bhh (r,z gates)
    __shared__ float sbni[20], sbnh[20];         // n-gate biases
    __shared__ int   sdst[NTHR];
    __shared__ __align__(16) float sbuf[NTHR * SB_STRIDE];

    const int tid = threadIdx.x;
    const int e = blockIdx.x * NTHR + tid;

    sdst[tid] = __ldg(dstv + e);
    for (int i = tid; i < 640; i += NTHR) sW1a[i] = W1[i] * LOG2E;
    if (COMPV) for (int i = tid; i < 640; i += NTHR) sW1b[i] = W1[640 + i] * LOG2E;
    for (int i = tid; i < 640; i += NTHR) sW2[i] = W2[i];
    if (tid < 32) sb1[tid] = b1[tid] * LOG2E;
    if (tid < 20) {
        sb2a[tid] = 16.0f * __ldg(b2 + tid) - 16.0f * ALPHA_S * g_colsum[tid];
        sbni[tid] = __ldg(bih + 40 + tid);
        sbnh[tid] = __ldg(bhh + 40 + tid);
    }
    if (tid < 40) sbc[tid] = __ldg(bih + tid) + __ldg(bhh + tid);
    __syncthreads();

    const float* vin  = parity ? g_v1 : g_v0;
    float*       vout = parity ? g_v0 : g_v1;
    const float* hin  = FIRST ? ea : g_h;

    // ---- phase 1: u' = h@W1a' + b1'  -> sbuf (8x STS.128). h regs die here.
    {
        u64 u2[16];
        const ulonglong2* bp = (const ulonglong2*)sb1;
#pragma unroll
        for (int q = 0; q < 8; q++) { ulonglong2 t = bp[q]; u2[2*q] = t.x; u2[2*q+1] = t.y; }
        const ulonglong2* hp = (const ulonglong2*)(hin + (size_t)e * 20);
#pragma unroll
        for (int q = 0; q < 5; q++) {
            ulonglong2 t = hp[q];
            float2 ha = unpack2(t.x), hb = unpack2(t.y);
            mv32p(u2, ha.x, sW1a + (4*q)   * 32);
            mv32p(u2, ha.y, sW1a + (4*q+1) * 32);
            mv32p(u2, hb.x, sW1a + (4*q+2) * 32);
            mv32p(u2, hb.y, sW1a + (4*q+3) * 32);
        }
        ulonglong2* sp = (ulonglong2*)(sbuf + tid * SB_STRIDE);
#pragma unroll
        for (int q = 0; q < 8; q++) { ulonglong2 t; t.x = u2[2*q]; t.y = u2[2*q+1]; sp[q] = t; }
    }
    __syncwarp();

    // ---- phase 2 (frozen R9 layout): pair-edge gather, software-pipelined
    // half-buffers. lanes 0-15 -> edge 2i, lanes 16-31 -> edge 2i+1; lane owns
    // a column pair. Lookahead index is masked (&127) instead of guarded:
    // last iteration prefetches a dead-but-valid row -> straight-line loop.
    //   sum selu(x) = C1*sum(x - min(x,0)) + ALPHA_S*sum 2^min(x,0)  (-16*ALPHA_S in sb2a)
    {
        const int lane  = tid & 31;
        const int wbase = tid & ~31;
        const int sub   = lane >> 4;
        const int c2    = (lane & 15) * 2;

        const u64* vrow = (const u64*)(vin + (size_t)sdst[wbase + sub] * 512 + c2);
        u64 buf0[8], buf1[8];
#pragma unroll
        for (int k = 0; k < 8; k++) buf0[k] = __ldg(vrow + k * 16);   // prologue

#pragma unroll 1
        for (int i = 0; i < 16; i++) {
            const int te = 2 * i + sub;
            float* srow = sbuf + (wbase + te) * SB_STRIDE + c2;
            const u64 uu2 = *(const u64*)srow;   // LDS.64 (own row/cols)

#pragma unroll
            for (int k = 0; k < 8; k++) buf1[k] = __ldg(vrow + (8 + k) * 16);

            u64 sx2 = 0ull;
            float sxm0 = 0.f, sxm1 = 0.f, t0 = 0.f, t1 = 0.f;
#pragma unroll
            for (int k = 0; k < 8; k++) {
                u64 x2 = add2(uu2, buf0[k]);
                float2 x = unpack2(x2);
                float xm0 = fminf(x.x, 0.0f);
                float xm1 = fminf(x.y, 0.0f);
                sx2 = add2(sx2, x2);
                sxm0 += xm0;  sxm1 += xm1;
                t0 += ex2f(xm0);  t1 += ex2f(xm1);
            }
            // unconditional lookahead (masked index; dead on final iteration)
            {
                const int nidx = (wbase + te + 2) & (NTHR - 1);
                vrow = (const u64*)(vin + (size_t)sdst[nidx] * 512 + c2);
#pragma unroll
                for (int k = 0; k < 8; k++) buf0[k] = __ldg(vrow + k * 16);
            }
#pragma unroll
            for (int k = 0; k < 8; k++) {
                u64 x2 = add2(uu2, buf1[k]);
                float2 x = unpack2(x2);
                float xm0 = fminf(x.x, 0.0f);
                float xm1 = fminf(x.y, 0.0f);
                sx2 = add2(sx2, x2);
                sxm0 += xm0;  sxm1 += xm1;
                t0 += ex2f(xm0);  t1 += ex2f(xm1);
            }
            float2 sx = unpack2(sx2);
            float s0 = fmaf(sx.x - sxm0, C1, t0 * ALPHA_S);
            float s1 = fmaf(sx.y - sxm1, C1, t1 * ALPHA_S);
            *(float2*)srow = make_float2(s0, s1);  // STS.64
        }
    }
    __syncwarp();

    // ---- reload own h row (L1-resident)
    u64 h2[10];
    {
        const ulonglong2* hp = (const ulonglong2*)(hin + (size_t)e * 20);
#pragma unroll
        for (int q = 0; q < 5; q++) { ulonglong2 t = hp[q]; h2[2*q] = t.x; h2[2*q+1] = t.y; }
    }

    // ---- phase 3: agg = s@W2 + adjusted bias
    u64 agg2[10];
    {
        const ulonglong2* bp = (const ulonglong2*)sb2a;
#pragma unroll
        for (int q = 0; q < 5; q++) { ulonglong2 t = bp[q]; agg2[2*q] = t.x; agg2[2*q+1] = t.y; }
#pragma unroll
        for (int cq = 0; cq < 8; cq++) {
            float sv[4];
            *(float4*)sv = *(const float4*)(sbuf + tid * SB_STRIDE + 4 * cq);
#pragma unroll
            for (int j = 0; j < 4; j++) {
                u64 sc2 = pack2(sv[j], sv[j]);
                const ulonglong2* w = (const ulonglong2*)(sW2 + (4 * cq + j) * 20);
#pragma unroll
                for (int qq = 0; qq < 5; qq++) {
                    ulonglong2 ww = w[qq];
                    agg2[2*qq]   = fma2(sc2, ww.x, agg2[2*qq]);
                    agg2[2*qq+1] = fma2(sc2, ww.y, agg2[2*qq+1]);
                }
            }
        }
    }

    // ---- GRU: fused r/z gate dots (dot40c), MUFU.TANH gates, hnew in registers
    float hnew[20];
#pragma unroll
    for (int op = 0; op < 10; op++) {
        float2 hh = unpack2(h2[op]);
#pragma unroll
        for (int j = 0; j < 2; j++) {
            int o = 2 * op + j;
            float hval = j ? hh.y : hh.x;
            float gr  = dot40c(o,      agg2, h2) + sbc[o];
            float gz  = dot40c(20 + o, agg2, h2) + sbc[20 + o];
            float inn = dot20c<true>(40 + o, agg2) + sbni[o];
            float hn  = dot20c<false>(40 + o, h2)  + sbnh[o];
            float r = sigmoid_t(gr);
            float z = sigmoid_t(gz);
            float n = tanhap(fmaf(r, hn, inn));
            hnew[o] = fmaf(z, hval - n, n);      // == (1-z)*n + z*h
        }
    }
    {
        float4* opn = (float4*)(g_h + (size_t)e * 20);
#pragma unroll
        for (int q = 0; q < 5; q++)
            opn[q] = make_float4(hnew[q*4], hnew[q*4+1], hnew[q*4+2], hnew[q*4+3]);
    }

    // ---- tail: v' for the NEXT step
    if (COMPV) {
        u64 v2[16];
#pragma unroll
        for (int c = 0; c < 16; c++) v2[c] = 0ull;
#pragma unroll
        for (int f = 0; f < 20; f++)
            mv32p(v2, hnew[f], sW1b + f * 32);
        ulonglong2* vp = (ulonglong2*)(vout + (size_t)e * 32);
#pragma unroll
        for (int q = 0; q < 8; q++) { ulonglong2 t; t.x = v2[2*q]; t.y = v2[2*q+1]; vp[q] = t; }
    }
}

// ---------------------------------------------------------------------------
__global__ void __launch_bounds__(NTHR) readout_kernel(
    const float* __restrict__ rW1, const float* __restrict__ rb1,
    const float* __restrict__ rW2, const float* __restrict__ rb2,
    const float* __restrict__ rW3, const float* __restrict__ rb3,
    float* __restrict__ out)
{
    __shared__ __align__(16) float sW1[20*64];
    __shared__ __align__(16) float sW2[64*32];
    __shared__ __align__(16) float sW3[32];
    __shared__ __align__(16) float sb1[64];
    __shared__ __align__(16) float sb2[32];
    __shared__ float sb3;

    const int tid = threadIdx.x;
    for (int i = tid; i < 20*64; i += NTHR) sW1[i] = rW1[i];
    for (int i = tid; i < 64*32; i += NTHR) sW2[i] = rW2[i];
    if (tid < 32) { sW3[tid] = rW3[tid]; sb2[tid] = rb2[tid]; }
    if (tid < 64) sb1[tid] = rb1[tid];
    if (tid == 0) sb3 = rb3[0];
    __syncthreads();

    const int e = blockIdx.x * NTHR + tid;
    float h[20];
    {
        const float4* hp = (const float4*)(g_h + (size_t)e * 20);
#pragma unroll
        for (int q = 0; q < 5; q++) {
            float4 t = hp[q];
            h[q*4+0]=t.x; h[q*4+1]=t.y; h[q*4+2]=t.z; h[q*4+3]=t.w;
        }
    }

    u64 x12[32];
    {
        const ulonglong2* bp = (const ulonglong2*)sb1;
#pragma unroll
        for (int q = 0; q < 16; q++) { ulonglong2 t = bp[q]; x12[2*q] = t.x; x12[2*q+1] = t.y; }
#pragma unroll
        for (int f = 0; f < 20; f++) {
            u64 hf2 = pack2(h[f], h[f]);
            const ulonglong2* w = (const ulonglong2*)(sW1 + f * 64);
#pragma unroll
            for (int q = 0; q < 16; q++) {
                ulonglong2 ww = w[q];
                x12[2*q]   = fma2(hf2, ww.x, x12[2*q]);
                x12[2*q+1] = fma2(hf2, ww.y, x12[2*q+1]);
            }
        }
    }
    float x1[64];
#pragma unroll
    for (int p = 0; p < 32; p++) {
        float2 t = unpack2(x12[p]);
        x1[2*p]   = selu_b(t.x);
        x1[2*p+1] = selu_b(t.y);
    }

    u64 x22[16];
    {
        const ulonglong2* bp = (const ulonglong2*)sb2;
#pragma unroll
        for (int q = 0; q < 8; q++) { ulonglong2 t = bp[q]; x22[2*q] = t.x; x22[2*q+1] = t.y; }
#pragma unroll
        for (int f = 0; f < 64; f++) {
            u64 xf2 = pack2(x1[f], x1[f]);
            const ulonglong2* w = (const ulonglong2*)(sW2 + f * 32);
#pragma unroll
            for (int q = 0; q < 8; q++) {
                ulonglong2 ww = w[q];
                x22[2*q]   = fma2(xf2, ww.x, x22[2*q]);
                x22[2*q+1] = fma2(xf2, ww.y, x22[2*q+1]);
            }
        }
    }

    float y = sb3;
#pragma unroll
    for (int p = 0; p < 16; p++) {
        float2 t = unpack2(x22[p]);
        y = fmaf(selu_b(t.x), sW3[2*p],   y);
        y = fmaf(selu_b(t.y), sW3[2*p+1], y);
    }

    float sp = (y > 20.0f) ? y : log1pf(__expf(y));
    float w  = sp + 0.1f;
    out[e] = fminf(fmaxf(w, 0.1f), 10.0f);
}

// ---------------------------------------------------------------------------
extern "C" void kernel_launch(void* const* d_in, const int* in_sizes, int n_in,
                              void* d_out, int out_size) {
    const float* ea  = (const float*)d_in[0];
    const float* W1  = (const float*)d_in[1];
    const float* b1  = (const float*)d_in[2];
    const float* W2  = (const float*)d_in[3];
    const float* b2  = (const float*)d_in[4];
    const float* Wih = (const float*)d_in[5];
    const float* Whh = (const float*)d_in[6];
    const float* bih = (const float*)d_in[7];
    const float* bhh = (const float*)d_in[8];
    const float* rW1 = (const float*)d_in[9];
    const float* rb1 = (const float*)d_in[10];
    const float* rW2 = (const float*)d_in[11];
    const float* rb2 = (const float*)d_in[12];
    const float* rW3 = (const float*)d_in[13];
    const float* rb3 = (const float*)d_in[14];
    const int*   eix = (const int*)d_in[15];
    const int*   dst = eix + E_EDGES;
    float* out = (float*)d_out;

    // GRU weights -> constant bank (device-to-device, graph-capturable)
    cudaMemcpyToSymbolAsync(cWih, Wih, 1200 * sizeof(float), 0, cudaMemcpyDeviceToDevice, 0);
    cudaMemcpyToSymbolAsync(cWhh, Whh, 1200 * sizeof(float), 0, cudaMemcpyDeviceToDevice, 0);

    kv_init<<<NBLK, NTHR>>>(ea, W1, W2);
    step_kernel<true,  true ><<<NBLK, NTHR>>>(ea, W1,b1,W2,b2,bih,bhh,dst, 0);
    step_kernel<false, true ><<<NBLK, NTHR>>>(ea, W1,b1,W2,b2,bih,bhh,dst, 1);
    step_kernel<false, true ><<<NBLK, NTHR>>>(ea, W1,b1,W2,b2,bih,bhh,dst, 0);
    step_kernel<false, false><<<NBLK, NTHR>>>(ea, W1,b1,W2,b2,bih,bhh,dst, 1);
    readout_kernel<<<NBLK, NTHR>>>(rW1,rb1,rW2,rb2,rW3,rb3, out);
}

// round 16
// speedup vs baseline: 1.0436x; 1.0436x over previous
#include <cuda_runtime.h>

typedef unsigned long long u64;

#define E_EDGES 320000
#define NTHR 128
#define NBLK (E_EDGES / NTHR)
#define SB_STRIDE 36   // floats; 144B rows, 16B-aligned

#define LOG2E   1.4426950408889634f
#define SELU_S  1.0507009873554805f
#define ALPHA_S 1.7580993408473766f                 // scale*alpha
#define C1      (1.0507009873554805f * 0.69314718055994530942f)  // s*ln2

// Scratch (device globals -- no allocation allowed)
__device__ __align__(16) float g_h [E_EDGES * 20];
__device__ __align__(16) float g_v0[E_EDGES * 32];
__device__ __align__(16) float g_v1[E_EDGES * 32];
__device__ __align__(16) float g_colsum[20];        // sum_c W2[c][o], computed once

// GRU weights in constant memory (populated via cudaMemcpyToSymbolAsync, D2D).
// ONLY the GRU lives here (R12: wider constant use serializes).
__constant__ ulonglong2 cWih[300];   // 60 rows x 20 floats
__constant__ ulonglong2 cWhh[300];

// ---- packed f32x2 helpers ----
__device__ __forceinline__ u64 fma2(u64 a, u64 b, u64 c) {
    u64 d; asm("fma.rn.f32x2 %0, %1, %2, %3;" : "=l"(d) : "l"(a), "l"(b), "l"(c)); return d;
}
__device__ __forceinline__ u64 add2(u64 a, u64 b) {
    u64 d; asm("add.rn.f32x2 %0, %1, %2;" : "=l"(d) : "l"(a), "l"(b)); return d;
}
__device__ __forceinline__ u64 pack2(float x, float y) {
    u64 d; asm("mov.b64 %0, {%1, %2};" : "=l"(d) : "f"(x), "f"(y)); return d;
}
__device__ __forceinline__ float2 unpack2(u64 v) {
    float2 r; asm("mov.b64 {%0, %1}, %2;" : "=f"(r.x), "=f"(r.y) : "l"(v)); return r;
}
__device__ __forceinline__ float ex2f(float x) {
    float y; asm("ex2.approx.f32 %0, %1;" : "=f"(y) : "f"(x)); return y;
}
__device__ __forceinline__ float tanhap(float x) {
    float y; asm("tanh.approx.f32 %0, %1;" : "=f"(y) : "f"(x)); return y;
}
__device__ __forceinline__ float sigmoid_t(float x) {
    return fmaf(tanhap(0.5f * x), 0.5f, 0.5f);   // exact identity, MUFU.TANH
}

// branchless SELU: m = min(x,0); selu = s*(x-m) + alpha_s*(2^(m*log2e) - 1)
__device__ __forceinline__ float selu_b(float x) {
    float m = fminf(x, 0.0f);
    return fmaf(SELU_S, x - m, fmaf(ALPHA_S, ex2f(m * LOG2E), -ALPHA_S));
}

// packed dot reading a 20-float row from __constant__
template<bool IH>
__device__ __forceinline__ float dot20c(int row, const u64* a) {
    u64 acc0 = 0ull, acc1 = 0ull;
#pragma unroll
    for (int q = 0; q < 5; q++) {
        ulonglong2 ww = IH ? cWih[row * 5 + q] : cWhh[row * 5 + q];
        acc0 = fma2(a[2*q],   ww.x, acc0);
        acc1 = fma2(a[2*q+1], ww.y, acc1);
    }
    float2 r0 = unpack2(acc0), r1 = unpack2(acc1);
    return (r0.x + r0.y) + (r1.x + r1.y);
}

// fused gate dot: wih_row . a  +  whh_row . b, one reduction
__device__ __forceinline__ float dot40c(int row, const u64* a, const u64* b) {
    u64 acc0 = 0ull, acc1 = 0ull;
#pragma unroll
    for (int q = 0; q < 5; q++) {
        ulonglong2 ww = cWih[row * 5 + q];
        acc0 = fma2(a[2*q],   ww.x, acc0);
        acc1 = fma2(a[2*q+1], ww.y, acc1);
    }
#pragma unroll
    for (int q = 0; q < 5; q++) {
        ulonglong2 ww = cWhh[row * 5 + q];
        acc0 = fma2(b[2*q],   ww.x, acc0);
        acc1 = fma2(b[2*q+1], ww.y, acc1);
    }
    float2 r0 = unpack2(acc0), r1 = unpack2(acc1);
    return (r0.x + r0.y) + (r1.x + r1.y);
}

// packed matvec: acc2[16] (32 outs) += hf * w_row[32]
__device__ __forceinline__ void mv32p(u64* acc2, float hf, const float* __restrict__ wrow) {
    u64 h2 = pack2(hf, hf);
    const ulonglong2* w = (const ulonglong2*)wrow;
#pragma unroll
    for (int q = 0; q < 8; q++) {
        ulonglong2 ww = w[q];
        acc2[2*q]   = fma2(h2, ww.x, acc2[2*q]);
        acc2[2*q+1] = fma2(h2, ww.y, acc2[2*q+1]);
    }
}

// vectorized staging of a 640-float weight array, optional scale
__device__ __forceinline__ void stage640(float* __restrict__ dst,
                                         const float* __restrict__ src,
                                         float scale, int tid) {
    const float4* s4 = (const float4*)src;
    float4* d4 = (float4*)dst;
#pragma unroll
    for (int i = tid; i < 160; i += NTHR) {
        float4 t = __ldg(s4 + i);
        t.x *= scale; t.y *= scale; t.z *= scale; t.w *= scale;
        d4[i] = t;
    }
}

// ---------------------------------------------------------------------------
__global__ void __launch_bounds__(NTHR) kv_init(const float* __restrict__ ea,
                                                const float* __restrict__ W1,
                                                const float* __restrict__ W2) {
    __shared__ __align__(16) float sW1b[640];
    stage640(sW1b, W1 + 640, LOG2E, threadIdx.x);
    // one block computes W2 column sums once for all step kernels
    if (blockIdx.x == 0 && threadIdx.x < 20) {
        float ssum = 0.0f;
#pragma unroll
        for (int c = 0; c < 32; c++) ssum += __ldg(W2 + c * 20 + threadIdx.x);
        g_colsum[threadIdx.x] = ssum;
    }
    __syncthreads();

    int e = blockIdx.x * NTHR + threadIdx.x;
    u64 h2[10];
    {
        const ulonglong2* hp = (const ulonglong2*)(ea + (size_t)e * 20);
#pragma unroll
        for (int q = 0; q < 5; q++) { ulonglong2 t = hp[q]; h2[2*q] = t.x; h2[2*q+1] = t.y; }
    }
    u64 v2[16];
#pragma unroll
    for (int c = 0; c < 16; c++) v2[c] = 0ull;
#pragma unroll
    for (int fp = 0; fp < 10; fp++) {
        float2 hh = unpack2(h2[fp]);
        mv32p(v2, hh.x, sW1b + (2*fp)   * 32);
        mv32p(v2, hh.y, sW1b + (2*fp+1) * 32);
    }
    ulonglong2* vp = (ulonglong2*)(g_v0 + (size_t)e * 32);
#pragma unroll
    for (int q = 0; q < 8; q++) { ulonglong2 t; t.x = v2[2*q]; t.y = v2[2*q+1]; vp[q] = t; }
}

// ---------------------------------------------------------------------------
template<bool FIRST, bool COMPV>
__global__ void __launch_bounds__(NTHR, 7) step_kernel(
    const float* __restrict__ ea,
    const float* __restrict__ W1,  const float* __restrict__ b1,
    const float* __restrict__ W2,  const float* __restrict__ b2,
    const float* __restrict__ bih, const float* __restrict__ bhh,
    const int*   __restrict__ dstv,
    int parity)
{
    __shared__ __align__(16) float sW1a[640];   // pre-scaled by log2e
    __shared__ __align__(16) float sW1b[640];   // pre-scaled by log2e
    __shared__ __align__(16) float sW2 [640];
    __shared__ __align__(16) float sb1[32];     // pre-scaled by log2e
    __shared__ __align__(16) float sb2a[20];    // 16*b2 - 16*ALPHA_S*colsum
    __shared__ float sbc[40];                    // bih+bhh (r,z gates)
    __shared__ float sbni[20], sbnh[20];         // n-gate biases
    __shared__ int   sdst[NTHR];
    __shared__ __align__(16) float sbuf[NTHR * SB_STRIDE];

    const int tid = threadIdx.x;
    const int e = blockIdx.x * NTHR + tid;

    sdst[tid] = __ldg(dstv + e);
    stage640(sW1a, W1, LOG2E, tid);
    if (COMPV) stage640(sW1b, W1 + 640, LOG2E, tid);
    stage640(sW2, W2, 1.0f, tid);
    if (tid < 32) sb1[tid] = b1[tid] * LOG2E;
    if (tid < 20) {
        sb2a[tid] = 16.0f * __ldg(b2 + tid) - 16.0f * ALPHA_S * g_colsum[tid];
        sbni[tid] = __ldg(bih + 40 + tid);
        sbnh[tid] = __ldg(bhh + 40 + tid);
    }
    if (tid < 40) sbc[tid] = __ldg(bih + tid) + __ldg(bhh + tid);
    __syncthreads();

    const float* vin  = parity ? g_v1 : g_v0;
    float*       vout = parity ? g_v0 : g_v1;
    const float* hin  = FIRST ? ea : g_h;

    // ---- phase 1: u' = h@W1a' + b1'  -> sbuf (8x STS.128). h regs die here.
    {
        u64 u2[16];
        const ulonglong2* bp = (const ulonglong2*)sb1;
#pragma unroll
        for (int q = 0; q < 8; q++) { ulonglong2 t = bp[q]; u2[2*q] = t.x; u2[2*q+1] = t.y; }
        const ulonglong2* hp = (const ulonglong2*)(hin + (size_t)e * 20);
#pragma unroll
        for (int q = 0; q < 5; q++) {
            ulonglong2 t = hp[q];
            float2 ha = unpack2(t.x), hb = unpack2(t.y);
            mv32p(u2, ha.x, sW1a + (4*q)   * 32);
            mv32p(u2, ha.y, sW1a + (4*q+1) * 32);
            mv32p(u2, hb.x, sW1a + (4*q+2) * 32);
            mv32p(u2, hb.y, sW1a + (4*q+3) * 32);
        }
        ulonglong2* sp = (ulonglong2*)(sbuf + tid * SB_STRIDE);
#pragma unroll
        for (int q = 0; q < 8; q++) { ulonglong2 t; t.x = u2[2*q]; t.y = u2[2*q+1]; sp[q] = t; }
    }
    __syncwarp();

    // ---- phase 2 (frozen R9/R14 layout): pair-edge gather, software-pipelined
    // half-buffers, GUARDED lookahead (predicated, proven). lanes 0-15 -> edge
    // 2i, lanes 16-31 -> edge 2i+1; lane owns a column pair.
    //   sum selu(x) = C1*sum(x - min(x,0)) + ALPHA_S*sum 2^min(x,0)  (-16*ALPHA_S in sb2a)
    {
        const int lane  = tid & 31;
        const int wbase = tid & ~31;
        const int sub   = lane >> 4;
        const int c2    = (lane & 15) * 2;

        const u64* vrow = (const u64*)(vin + (size_t)sdst[wbase + sub] * 512 + c2);
        u64 buf0[8], buf1[8];
#pragma unroll
        for (int k = 0; k < 8; k++) buf0[k] = __ldg(vrow + k * 16);   // prologue

#pragma unroll 1
        for (int i = 0; i < 16; i++) {
            const int te = 2 * i + sub;
            float* srow = sbuf + (wbase + te) * SB_STRIDE + c2;
            const u64 uu2 = *(const u64*)srow;   // LDS.64 (own row/cols)

#pragma unroll
            for (int k = 0; k < 8; k++) buf1[k] = __ldg(vrow + (8 + k) * 16);

            u64 sx2 = 0ull;
            float sxm0 = 0.f, sxm1 = 0.f, t0 = 0.f, t1 = 0.f;
#pragma unroll
            for (int k = 0; k < 8; k++) {
                u64 x2 = add2(uu2, buf0[k]);
                float2 x = unpack2(x2);
                float xm0 = fminf(x.x, 0.0f);
                float xm1 = fminf(x.y, 0.0f);
                sx2 = add2(sx2, x2);
                sxm0 += xm0;  sxm1 += xm1;
                t0 += ex2f(xm0);  t1 += ex2f(xm1);
            }
            if (i < 15) {
                vrow = (const u64*)(vin + (size_t)sdst[wbase + te + 2] * 512 + c2);
#pragma unroll
                for (int k = 0; k < 8; k++) buf0[k] = __ldg(vrow + k * 16);
            }
#pragma unroll
            for (int k = 0; k < 8; k++) {
                u64 x2 = add2(uu2, buf1[k]);
                float2 x = unpack2(x2);
                float xm0 = fminf(x.x, 0.0f);
                float xm1 = fminf(x.y, 0.0f);
                sx2 = add2(sx2, x2);
                sxm0 += xm0;  sxm1 += xm1;
                t0 += ex2f(xm0);  t1 += ex2f(xm1);
            }
            float2 sx = unpack2(sx2);
            float s0 = fmaf(sx.x - sxm0, C1, t0 * ALPHA_S);
            float s1 = fmaf(sx.y - sxm1, C1, t1 * ALPHA_S);
            *(float2*)srow = make_float2(s0, s1);  // STS.64
        }
    }
    __syncwarp();

    // ---- reload own h row (L1-resident)
    u64 h2[10];
    {
        const ulonglong2* hp = (const ulonglong2*)(hin + (size_t)e * 20);
#pragma unroll
        for (int q = 0; q < 5; q++) { ulonglong2 t = hp[q]; h2[2*q] = t.x; h2[2*q+1] = t.y; }
    }

    // ---- phase 3: agg = s@W2 + adjusted bias
    u64 agg2[10];
    {
        const ulonglong2* bp = (const ulonglong2*)sb2a;
#pragma unroll
        for (int q = 0; q < 5; q++) { ulonglong2 t = bp[q]; agg2[2*q] = t.x; agg2[2*q+1] = t.y; }
#pragma unroll
        for (int cq = 0; cq < 8; cq++) {
            float sv[4];
            *(float4*)sv = *(const float4*)(sbuf + tid * SB_STRIDE + 4 * cq);
#pragma unroll
            for (int j = 0; j < 4; j++) {
                u64 sc2 = pack2(sv[j], sv[j]);
                const ulonglong2* w = (const ulonglong2*)(sW2 + (4 * cq + j) * 20);
#pragma unroll
                for (int qq = 0; qq < 5; qq++) {
                    ulonglong2 ww = w[qq];
                    agg2[2*qq]   = fma2(sc2, ww.x, agg2[2*qq]);
                    agg2[2*qq+1] = fma2(sc2, ww.y, agg2[2*qq+1]);
                }
            }
        }
    }

    // ---- GRU: fused r/z gate dots (dot40c), MUFU.TANH gates, hnew in registers
    float hnew[20];
#pragma unroll
    for (int op = 0; op < 10; op++) {
        float2 hh = unpack2(h2[op]);
#pragma unroll
        for (int j = 0; j < 2; j++) {
            int o = 2 * op + j;
            float hval = j ? hh.y : hh.x;
            float gr  = dot40c(o,      agg2, h2) + sbc[o];
            float gz  = dot40c(20 + o, agg2, h2) + sbc[20 + o];
            float inn = dot20c<true>(40 + o, agg2) + sbni[o];
            float hn  = dot20c<false>(40 + o, h2)  + sbnh[o];
            float r = sigmoid_t(gr);
            float z = sigmoid_t(gz);
            float n = tanhap(fmaf(r, hn, inn));
            hnew[o] = fmaf(z, hval - n, n);      // == (1-z)*n + z*h
        }
    }
    {
        float4* opn = (float4*)(g_h + (size_t)e * 20);
#pragma unroll
        for (int q = 0; q < 5; q++)
            opn[q] = make_float4(hnew[q*4], hnew[q*4+1], hnew[q*4+2], hnew[q*4+3]);
    }

    // ---- tail: v' for the NEXT step
    if (COMPV) {
        u64 v2[16];
#pragma unroll
        for (int c = 0; c < 16; c++) v2[c] = 0ull;
#pragma unroll
        for (int f = 0; f < 20; f++)
            mv32p(v2, hnew[f], sW1b + f * 32);
        ulonglong2* vp = (ulonglong2*)(vout + (size_t)e * 32);
#pragma unroll
        for (int q = 0; q < 8; q++) { ulonglong2 t; t.x = v2[2*q]; t.y = v2[2*q+1]; vp[q] = t; }
    }
}

// ---------------------------------------------------------------------------
__global__ void __launch_bounds__(NTHR) readout_kernel(
    const float* __restrict__ rW1, const float* __restrict__ rb1,
    const float* __restrict__ rW2, const float* __restrict__ rb2,
    const float* __restrict__ rW3, const float* __restrict__ rb3,
    float* __restrict__ out)
{
    __shared__ __align__(16) float sW1[20*64];
    __shared__ __align__(16) float sW2[64*32];
    __shared__ __align__(16) float sW3[32];
    __shared__ __align__(16) float sb1[64];
    __shared__ __align__(16) float sb2[32];
    __shared__ float sb3;

    const int tid = threadIdx.x;
    {
        const float4* s4 = (const float4*)rW1;
        float4* d4 = (float4*)sW1;
#pragma unroll
        for (int i = tid; i < 320; i += NTHR) d4[i] = __ldg(s4 + i);
    }
    {
        const float4* s4 = (const float4*)rW2;
        float4* d4 = (float4*)sW2;
#pragma unroll
        for (int i = tid; i < 512; i += NTHR) d4[i] = __ldg(s4 + i);
    }
    if (tid < 32) { sW3[tid] = rW3[tid]; sb2[tid] = rb2[tid]; }
    if (tid < 64) sb1[tid] = rb1[tid];
    if (tid == 0) sb3 = rb3[0];
    __syncthreads();

    const int e = blockIdx.x * NTHR + tid;
    float h[20];
    {
        const float4* hp = (const float4*)(g_h + (size_t)e * 20);
#pragma unroll
        for (int q = 0; q < 5; q++) {
            float4 t = hp[q];
            h[q*4+0]=t.x; h[q*4+1]=t.y; h[q*4+2]=t.z; h[q*4+3]=t.w;
        }
    }

    u64 x12[32];
    {
        const ulonglong2* bp = (const ulonglong2*)sb1;
#pragma unroll
        for (int q = 0; q < 16; q++) { ulonglong2 t = bp[q]; x12[2*q] = t.x; x12[2*q+1] = t.y; }
#pragma unroll
        for (int f = 0; f < 20; f++) {
            u64 hf2 = pack2(h[f], h[f]);
            const ulonglong2* w = (const ulonglong2*)(sW1 + f * 64);
#pragma unroll
            for (int q = 0; q < 16; q++) {
                ulonglong2 ww = w[q];
                x12[2*q]   = fma2(hf2, ww.x, x12[2*q]);
                x12[2*q+1] = fma2(hf2, ww.y, x12[2*q+1]);
            }
        }
    }
    float x1[64];
#pragma unroll
    for (int p = 0; p < 32; p++) {
        float2 t = unpack2(x12[p]);
        x1[2*p]   = selu_b(t.x);
        x1[2*p+1] = selu_b(t.y);
    }

    u64 x22[16];
    {
        const ulonglong2* bp = (const ulonglong2*)sb2;
#pragma unroll
        for (int q = 0; q < 8; q++) { ulonglong2 t = bp[q]; x22[2*q] = t.x; x22[2*q+1] = t.y; }
#pragma unroll
        for (int f = 0; f < 64; f++) {
            u64 xf2 = pack2(x1[f], x1[f]);
            const ulonglong2* w = (const ulonglong2*)(sW2 + f * 32);
#pragma unroll
            for (int q = 0; q < 8; q++) {
                ulonglong2 ww = w[q];
                x22[2*q]   = fma2(xf2, ww.x, x22[2*q]);
                x22[2*q+1] = fma2(xf2, ww.y, x22[2*q+1]);
            }
        }
    }

    float y = sb3;
#pragma unroll
    for (int p = 0; p < 16; p++) {
        float2 t = unpack2(x22[p]);
        y = fmaf(selu_b(t.x), sW3[2*p],   y);
        y = fmaf(selu_b(t.y), sW3[2*p+1], y);
    }

    float sp = (y > 20.0f) ? y : log1pf(__expf(y));
    float w  = sp + 0.1f;
    out[e] = fminf(fmaxf(w, 0.1f), 10.0f);
}

// ---------------------------------------------------------------------------
extern "C" void kernel_launch(void* const* d_in, const int* in_sizes, int n_in,
                              void* d_out, int out_size) {
    const float* ea  = (const float*)d_in[0];
    const float* W1  = (const float*)d_in[1];
    const float* b1  = (const float*)d_in[2];
    const float* W2  = (const float*)d_in[3];
    const float* b2  = (const float*)d_in[4];
    const float* Wih = (const float*)d_in[5];
    const float* Whh = (const float*)d_in[6];
    const float* bih = (const float*)d_in[7];
    const float* bhh = (const float*)d_in[8];
    const float* rW1 = (const float*)d_in[9];
    const float* rb1 = (const float*)d_in[10];
    const float* rW2 = (const float*)d_in[11];
    const float* rb2 = (const float*)d_in[12];
    const float* rW3 = (const float*)d_in[13];
    const float* rb3 = (const float*)d_in[14];
    const int*   eix = (const int*)d_in[15];
    const int*   dst = eix + E_EDGES;
    float* out = (float*)d_out;

    // GRU weights -> constant bank (device-to-device, graph-capturable)
    cudaMemcpyToSymbolAsync(cWih, Wih, 1200 * sizeof(float), 0, cudaMemcpyDeviceToDevice, 0);
    cudaMemcpyToSymbolAsync(cWhh, Whh, 1200 * sizeof(float), 0, cudaMemcpyDeviceToDevice, 0);

    kv_init<<<NBLK, NTHR>>>(ea, W1, W2);
    step_kernel<true,  true ><<<NBLK, NTHR>>>(ea, W1,b1,W2,b2,bih,bhh,dst, 0);
    step_kernel<false, true ><<<NBLK, NTHR>>>(ea, W1,b1,W2,b2,bih,bhh,dst, 1);
    step_kernel<false, true ><<<NBLK, NTHR>>>(ea, W1,b1,W2,b2,bih,bhh,dst, 0);
    step_kernel<false, false><<<NBLK, NTHR>>>(ea, W1,b1,W2,b2,bih,bhh,dst, 1);
    readout_kernel<<<NBLK, NTHR>>>(rW1,rb1,rW2,rb2,rW3,rb3, out);
}